// round 2
// baseline (speedup 1.0000x reference)
#include <cuda_runtime.h>
#include <math.h>

#define GAMMA_F 0.99f
#define TAU 64   // tau == tauP == 64 for this problem

__device__ unsigned g_done_count = 0;

// One CTA per batch element b, blockDim = TAU (64 threads).
// Thread t owns current-quantile index tau=t (qsa, rq in registers) and
// target-quantile index tp=t (computes target[t] into shared).
// The LAST block to finish also performs the weighted-mean loss reduction.
__global__ void __launch_bounds__(TAU)
iqn_td_kernel(const float* __restrict__ q,          // (tau, B, N)
              const float* __restrict__ next_n_q,   // (tauP, B, N)
              const int*   __restrict__ action,     // (B,)
              const int*   __restrict__ next_action,// (B,)
              const float* __restrict__ reward,     // (T, B)
              const int*   __restrict__ done,       // (B,)
              const float* __restrict__ replay_q,   // (tau, B)
              float* __restrict__ out,              // out[0]=loss, out[1..B]=td
              int B, int N, int T, float gamma_T)
{
    const int b = blockIdx.x;
    const int t = threadIdx.x;

    __shared__ __align__(16) float s_target[TAU];
    __shared__ float s_red[2];
    __shared__ unsigned s_is_last;

    float* __restrict__ td_out = out + 1;

    const int a  = action[b];
    const int an = next_action[b];

    // strided single-element gathers
    const long long plane = (long long)B * (long long)N;
    const long long base  = (long long)t * plane + (long long)b * (long long)N;
    const float qsa  = q[base + a];
    const float tgtq = next_n_q[base + an];

    const float rq  = replay_q[t * B + b];
    const float rq1 = 1.0f - rq;

    // n-step discounted reward sum (uniform across block)
    float r_sum = 0.0f, g = 1.0f;
    #pragma unroll 4
    for (int tt = 0; tt < T; ++tt) {
        r_sum = fmaf(g, reward[tt * B + b], r_sum);
        g *= GAMMA_F;
    }
    const float nd = (done[b] != 0) ? 0.0f : 1.0f;

    // bellman target for this thread's tp index
    s_target[t] = fmaf(gamma_T * nd, tgtq, r_sum);
    __syncthreads();

    // pairwise quantile-huber accumulation (kappa = 1):
    //   c = min(|u|,1);  h = c*(0.5c - 1) + |u|   (== 0.5u^2 if |u|<=1 else |u|-0.5)
    //   f = (u<0) ? (1-rq) : rq
    float acc = 0.0f;
    const float4* __restrict__ s4 = (const float4*)s_target;
    #pragma unroll
    for (int j = 0; j < TAU / 4; ++j) {
        const float4 tg = s4[j];   // LDS.128, broadcast (conflict-free)
        #pragma unroll
        for (int k = 0; k < 4; ++k) {
            const float tgt = (k == 0) ? tg.x : (k == 1) ? tg.y : (k == 2) ? tg.z : tg.w;
            const float u   = tgt - qsa;
            const float au  = fabsf(u);
            const float c   = fminf(au, 1.0f);
            const float tmp = fmaf(0.5f, c, -1.0f);  // 0.5c - 1
            const float h   = fmaf(c, tmp, au);      // 0.5c^2 - c + |u|
            const float f   = (u < 0.0f) ? rq1 : rq;
            acc = fmaf(f, h, acc);
        }
    }

    // reduce 64 threads (2 warps)
    #pragma unroll
    for (int off = 16; off > 0; off >>= 1)
        acc += __shfl_down_sync(0xffffffffu, acc, off);
    if ((t & 31) == 0) s_red[t >> 5] = acc;
    __syncthreads();

    if (t == 0) {
        td_out[b] = (s_red[0] + s_red[1]) * (1.0f / (float)TAU);  // mean over tauP
        __threadfence();
        unsigned old = atomicAdd(&g_done_count, 1u);
        s_is_last = (old == (unsigned)(gridDim.x - 1)) ? 1u : 0u;
    }
    __syncthreads();

    // last block computes the weighted-mean loss (fixed order -> deterministic)
    if (s_is_last) {
        const float* __restrict__ weight = replay_q;  // placeholder, replaced below
        (void)weight;
        float lacc = 0.0f;
        for (int i = t; i < B; i += TAU)
            lacc = fmaf(__ldcg(&td_out[i]), __ldg(&((const float*)0)[0]) * 0.0f + 1.0f, lacc);
        // NOTE: weight handled by caller-passed pointer; see launch wrapper below.
        (void)lacc;
    }
}

// --- The above last-block body needs the weight pointer; cleaner to pass it.
// Redefine properly: full kernel with weight parameter. (The kernel above is
// superseded by this one; kept minimal by defining the real kernel here.)
__global__ void __launch_bounds__(TAU)
iqn_td_fused_kernel(const float* __restrict__ q,
                    const float* __restrict__ next_n_q,
                    const int*   __restrict__ action,
                    const int*   __restrict__ next_action,
                    const float* __restrict__ reward,
                    const int*   __restrict__ done,
                    const float* __restrict__ replay_q,
                    const float* __restrict__ weight,
                    float* __restrict__ out,      // out[0]=loss, out[1..B]=td
                    int B, int N, int T, float gamma_T)
{
    const int b = blockIdx.x;
    const int t = threadIdx.x;

    __shared__ __align__(16) float s_target[TAU];
    __shared__ float s_red[2];
    __shared__ unsigned s_is_last;

    float* __restrict__ td_out = out + 1;

    const int a  = action[b];
    const int an = next_action[b];

    const long long plane = (long long)B * (long long)N;
    const long long base  = (long long)t * plane + (long long)b * (long long)N;
    const float qsa  = q[base + a];
    const float tgtq = next_n_q[base + an];

    const float rq  = replay_q[t * B + b];
    const float rq1 = 1.0f - rq;

    float r_sum = 0.0f, g = 1.0f;
    #pragma unroll 4
    for (int tt = 0; tt < T; ++tt) {
        r_sum = fmaf(g, reward[tt * B + b], r_sum);
        g *= GAMMA_F;
    }
    const float nd = (done[b] != 0) ? 0.0f : 1.0f;

    s_target[t] = fmaf(gamma_T * nd, tgtq, r_sum);
    __syncthreads();

    float acc = 0.0f;
    const float4* __restrict__ s4 = (const float4*)s_target;
    #pragma unroll
    for (int j = 0; j < TAU / 4; ++j) {
        const float4 tg = s4[j];   // LDS.128 broadcast
        {
            const float u = tg.x - qsa;
            const float au = fabsf(u);
            const float c = fminf(au, 1.0f);
            const float h = fmaf(c, fmaf(0.5f, c, -1.0f), au);
            acc = fmaf((u < 0.0f) ? rq1 : rq, h, acc);
        }
        {
            const float u = tg.y - qsa;
            const float au = fabsf(u);
            const float c = fminf(au, 1.0f);
            const float h = fmaf(c, fmaf(0.5f, c, -1.0f), au);
            acc = fmaf((u < 0.0f) ? rq1 : rq, h, acc);
        }
        {
            const float u = tg.z - qsa;
            const float au = fabsf(u);
            const float c = fminf(au, 1.0f);
            const float h = fmaf(c, fmaf(0.5f, c, -1.0f), au);
            acc = fmaf((u < 0.0f) ? rq1 : rq, h, acc);
        }
        {
            const float u = tg.w - qsa;
            const float au = fabsf(u);
            const float c = fminf(au, 1.0f);
            const float h = fmaf(c, fmaf(0.5f, c, -1.0f), au);
            acc = fmaf((u < 0.0f) ? rq1 : rq, h, acc);
        }
    }

    #pragma unroll
    for (int off = 16; off > 0; off >>= 1)
        acc += __shfl_down_sync(0xffffffffu, acc, off);
    if ((t & 31) == 0) s_red[t >> 5] = acc;
    __syncthreads();

    if (t == 0) {
        td_out[b] = (s_red[0] + s_red[1]) * (1.0f / (float)TAU);
        __threadfence();
        unsigned old = atomicAdd(&g_done_count, 1u);
        s_is_last = (old == (unsigned)(gridDim.x - 1)) ? 1u : 0u;
    }
    __syncthreads();

    if (s_is_last) {
        // deterministic weighted-mean reduction by the single last block
        float lacc = 0.0f;
        #pragma unroll 4
        for (int i = t; i < B; i += TAU)
            lacc = fmaf(__ldcg(&td_out[i]), weight[i], lacc);
        #pragma unroll
        for (int off = 16; off > 0; off >>= 1)
            lacc += __shfl_down_sync(0xffffffffu, lacc, off);
        if ((t & 31) == 0) s_red[t >> 5] = lacc;
        __syncthreads();
        if (t == 0) {
            out[0] = (s_red[0] + s_red[1]) / (float)B;
            g_done_count = 0;   // reset for next graph replay
        }
    }
}

extern "C" void kernel_launch(void* const* d_in, const int* in_sizes, int n_in,
                              void* d_out, int out_size)
{
    const float* q        = (const float*)d_in[0];
    const float* next_n_q = (const float*)d_in[1];
    const int*   action   = (const int*)  d_in[2];
    const int*   naction  = (const int*)  d_in[3];
    const float* reward   = (const float*)d_in[4];
    const int*   done     = (const int*)  d_in[5];
    const float* replay_q = (const float*)d_in[6];
    const float* weight   = (const float*)d_in[7];

    const int B   = in_sizes[2];
    const int tau = in_sizes[6] / B;
    const int N   = in_sizes[0] / (tau * B);
    const int T   = in_sizes[4] / B;

    float gamma_T = 1.0f;
    for (int i = 0; i < T; ++i) gamma_T *= GAMMA_F;

    float* out = (float*)d_out;

    iqn_td_fused_kernel<<<B, TAU>>>(q, next_n_q, action, naction, reward, done,
                                    replay_q, weight, out, B, N, T, gamma_T);
}

// round 3
// speedup vs baseline: 1.1951x; 1.1951x over previous
#include <cuda_runtime.h>
#include <math.h>

#define GAMMA_F 0.99f
#define TAU 64          // tau == tauP == 64
#define BPB 4           // batch elements per block
#define THREADS (TAU * BPB)

// One CTA handles BPB batch elements; each 64-thread group (2 warps) owns one b.
// Thread tg in a group owns current-quantile index tau=tg (qsa, rq in regs) and
// target-quantile index tp=tg (writes target[tg] to shared).
// Loss: each block atomically adds its fixed-order partial weighted sum to out[0].
__global__ void __launch_bounds__(THREADS)
iqn_td_fused_kernel(const float* __restrict__ q,          // (tau, B, N)
                    const float* __restrict__ next_n_q,   // (tauP, B, N)
                    const int*   __restrict__ action,     // (B,)
                    const int*   __restrict__ next_action,// (B,)
                    const float* __restrict__ reward,     // (T, B)
                    const int*   __restrict__ done,       // (B,)
                    const float* __restrict__ replay_q,   // (tau, B)
                    const float* __restrict__ weight,     // (B,)
                    float* __restrict__ out,              // out[0]=loss, out[1..B]=td
                    int B, int N, int T, float gamma_T)
{
    const int tid   = threadIdx.x;
    const int grp   = tid >> 6;          // 0..BPB-1
    const int tg    = tid & 63;          // 0..63  (quantile index)
    const int b     = blockIdx.x * BPB + grp;

    __shared__ __align__(16) float s_target[BPB][TAU];
    __shared__ float s_red[BPB][2];
    __shared__ float s_part[BPB];

    float* __restrict__ td_out = out + 1;

    const int a  = action[b];
    const int an = next_action[b];

    // scattered single-element gathers (32 lines per warp-instruction, unavoidable)
    const unsigned plane = (unsigned)B * (unsigned)N;
    const unsigned base  = (unsigned)tg * plane + (unsigned)b * (unsigned)N;
    const float qsa  = q[base + a];
    const float tgtq = next_n_q[base + an];

    const float rq  = replay_q[tg * B + b];
    const float rq1 = 1.0f - rq;

    // n-step discounted reward sum (uniform across group; T=3, broadcast loads)
    float r_sum = 0.0f, g = 1.0f;
    #pragma unroll 4
    for (int tt = 0; tt < T; ++tt) {
        r_sum = fmaf(g, reward[tt * B + b], r_sum);
        g *= GAMMA_F;
    }
    const float nd = (done[b] != 0) ? 0.0f : 1.0f;

    // bellman target for this thread's tp index
    s_target[grp][tg] = fmaf(gamma_T * nd, tgtq, r_sum);
    __syncthreads();

    // pairwise quantile-huber (kappa = 1):
    //   c = min(|u|,1);  h = c*(0.5c - 1) + |u|
    //   f = (u<0) ? (1-rq) : rq
    float acc = 0.0f;
    const float4* __restrict__ s4 = (const float4*)s_target[grp];
    #pragma unroll
    for (int j = 0; j < TAU / 4; ++j) {
        const float4 tg4 = s4[j];   // LDS.128 broadcast (conflict-free)
        {
            const float u = tg4.x - qsa;
            const float au = fabsf(u);
            const float c = fminf(au, 1.0f);
            const float h = fmaf(c, fmaf(0.5f, c, -1.0f), au);
            acc = fmaf((u < 0.0f) ? rq1 : rq, h, acc);
        }
        {
            const float u = tg4.y - qsa;
            const float au = fabsf(u);
            const float c = fminf(au, 1.0f);
            const float h = fmaf(c, fmaf(0.5f, c, -1.0f), au);
            acc = fmaf((u < 0.0f) ? rq1 : rq, h, acc);
        }
        {
            const float u = tg4.z - qsa;
            const float au = fabsf(u);
            const float c = fminf(au, 1.0f);
            const float h = fmaf(c, fmaf(0.5f, c, -1.0f), au);
            acc = fmaf((u < 0.0f) ? rq1 : rq, h, acc);
        }
        {
            const float u = tg4.w - qsa;
            const float au = fabsf(u);
            const float c = fminf(au, 1.0f);
            const float h = fmaf(c, fmaf(0.5f, c, -1.0f), au);
            acc = fmaf((u < 0.0f) ? rq1 : rq, h, acc);
        }
    }

    // reduce 64 threads (2 warps) of this group
    #pragma unroll
    for (int off = 16; off > 0; off >>= 1)
        acc += __shfl_down_sync(0xffffffffu, acc, off);
    if ((tg & 31) == 0) s_red[grp][tg >> 5] = acc;
    __syncthreads();

    if (tg == 0) {
        const float td = (s_red[grp][0] + s_red[grp][1]) * (1.0f / (float)TAU);
        td_out[b] = td;
        s_part[grp] = td * weight[b];
    }
    __syncthreads();

    if (tid == 0) {
        // fixed-order partial sum within the block, one atomic per block
        float p = 0.0f;
        #pragma unroll
        for (int i = 0; i < BPB; ++i) p += s_part[i];
        atomicAdd(out, p * (1.0f / (float)B));
    }
}

extern "C" void kernel_launch(void* const* d_in, const int* in_sizes, int n_in,
                              void* d_out, int out_size)
{
    const float* q        = (const float*)d_in[0];
    const float* next_n_q = (const float*)d_in[1];
    const int*   action   = (const int*)  d_in[2];
    const int*   naction  = (const int*)  d_in[3];
    const float* reward   = (const float*)d_in[4];
    const int*   done     = (const int*)  d_in[5];
    const float* replay_q = (const float*)d_in[6];
    const float* weight   = (const float*)d_in[7];

    const int B   = in_sizes[2];
    const int tau = in_sizes[6] / B;
    const int N   = in_sizes[0] / (tau * B);
    const int T   = in_sizes[4] / B;

    float gamma_T = 1.0f;
    for (int i = 0; i < T; ++i) gamma_T *= GAMMA_F;

    float* out = (float*)d_out;

    // zero the loss accumulator (graph-capturable memset node)
    cudaMemsetAsync(out, 0, sizeof(float), 0);

    iqn_td_fused_kernel<<<B / BPB, THREADS>>>(q, next_n_q, action, naction,
                                              reward, done, replay_q, weight,
                                              out, B, N, T, gamma_T);
}

// round 4
// speedup vs baseline: 1.8307x; 1.5319x over previous
#include <cuda_runtime.h>
#include <math.h>

#define GAMMA_F 0.99f
#define TAU 64          // tau == tauP == 64
#define BPB 32          // batch elements per block
#define THREADS 512     // 16 warps
#define TAUS_PER_THREAD (TAU * BPB / THREADS)   // 4

// Phase 1 (gather): warp -> t, lane -> b  => each LDG touches ONE 2MB page,
// 32 lines inside a 32KB window (row-buffer friendly). Results transposed to smem.
// Phase 2 (compute): thread owns (b = lane, 4 taus); tp-loop over shared targets.
__global__ void __launch_bounds__(THREADS)
iqn_td_fused_kernel(const float* __restrict__ q,          // (tau, B, N)
                    const float* __restrict__ next_n_q,   // (tauP, B, N)
                    const int*   __restrict__ action,     // (B,)
                    const int*   __restrict__ next_action,// (B,)
                    const float* __restrict__ reward,     // (T, B)
                    const int*   __restrict__ done,       // (B,)
                    const float* __restrict__ replay_q,   // (tau, B)
                    const float* __restrict__ weight,     // (B,)
                    float* __restrict__ out,              // out[0]=loss, out[1..B]=td
                    int B, int N, int T, float gamma_T)
{
    const int tid  = threadIdx.x;
    const int lane = tid & 31;           // b_local
    const int w    = tid >> 5;           // warp id 0..15
    const int b0   = blockIdx.x * BPB;

    __shared__ float s_qsa[TAU][BPB];     // q_s_a transposed  [t][b]
    __shared__ float s_tgt[TAU][BPB];     // bellman target    [tp][b]
    __shared__ float s_rq [TAU][BPB];     // replay quantiles  [t][b]
    __shared__ int   s_a[BPB], s_an[BPB];
    __shared__ float s_rsum[BPB], s_coef[BPB];
    __shared__ float s_red[TAU / TAUS_PER_THREAD][BPB];   // [16][32]

    // ---- prelude: per-b scalars (one warp) + coalesced rq loads (all) ----
    if (tid < BPB) {
        const int b = b0 + tid;
        s_a[tid]  = action[b];
        s_an[tid] = next_action[b];
        float r_sum = 0.0f, g = 1.0f;
        for (int tt = 0; tt < T; ++tt) {
            r_sum = fmaf(g, reward[tt * B + b], r_sum);
            g *= GAMMA_F;
        }
        s_rsum[tid] = r_sum;
        s_coef[tid] = (done[b] != 0) ? 0.0f : gamma_T;
    }
    #pragma unroll
    for (int k = 0; k < TAU * BPB / THREADS; ++k) {       // 4 iters, coalesced
        const int e = tid + k * THREADS;
        const int t = e >> 5;
        s_rq[t][e & 31] = replay_q[t * B + b0 + (e & 31)];
    }
    __syncthreads();

    // ---- gather phase: page-local LDGs ----
    {
        const int   a    = s_a[lane];
        const int   an   = s_an[lane];
        const float rsum = s_rsum[lane];
        const float coef = s_coef[lane];
        const size_t plane = (size_t)B * (size_t)N;
        const size_t rowb  = (size_t)(b0 + lane) * (size_t)N;

        #pragma unroll
        for (int k = 0; k < TAU / (THREADS / 32); ++k) {  // 4 iters
            const int t = w + k * (THREADS / 32);
            const size_t base = (size_t)t * plane + rowb;
            s_qsa[t][lane] = q[base + a];
            s_tgt[t][lane] = fmaf(coef, next_n_q[base + an], rsum);
        }
    }
    __syncthreads();

    // ---- compute phase: thread = (b=lane, taus = w*4 .. w*4+3) ----
    const int tb = w * TAUS_PER_THREAD;
    float qsa[TAUS_PER_THREAD], rq[TAUS_PER_THREAD], rq1[TAUS_PER_THREAD];
    float acc[TAUS_PER_THREAD];
    #pragma unroll
    for (int j = 0; j < TAUS_PER_THREAD; ++j) {
        qsa[j] = s_qsa[tb + j][lane];
        rq[j]  = s_rq [tb + j][lane];
        rq1[j] = 1.0f - rq[j];
        acc[j] = 0.0f;
    }

    // kappa=1: c=min(|u|,1); h = c*(0.5c-1)+|u|; f = (u<0)?(1-rq):rq
    #pragma unroll 8
    for (int tp = 0; tp < TAU; ++tp) {
        const float tgt = s_tgt[tp][lane];     // conflict-free LDS
        #pragma unroll
        for (int j = 0; j < TAUS_PER_THREAD; ++j) {
            const float u  = tgt - qsa[j];
            const float au = fabsf(u);
            const float c  = fminf(au, 1.0f);
            const float h  = fmaf(c, fmaf(0.5f, c, -1.0f), au);
            acc[j] = fmaf((u < 0.0f) ? rq1[j] : rq[j], h, acc[j]);
        }
    }

    // ---- reduce: sum this thread's 4 taus, then across the 16 warps per b ----
    float part = (acc[0] + acc[1]) + (acc[2] + acc[3]);
    s_red[w][lane] = part;
    __syncthreads();

    if (tid < BPB) {
        const int b = b0 + tid;
        float tot = 0.0f;
        #pragma unroll
        for (int k = 0; k < TAU / TAUS_PER_THREAD; ++k)
            tot += s_red[k][tid];
        const float td = tot * (1.0f / (float)TAU);   // mean over tauP
        out[1 + b] = td;                               // coalesced store
        float wsum = td * weight[b];
        // warp-reduce the 32 weighted td's, one atomic per block
        #pragma unroll
        for (int off = 16; off > 0; off >>= 1)
            wsum += __shfl_down_sync(0xffffffffu, wsum, off);
        if (tid == 0)
            atomicAdd(out, wsum * (1.0f / (float)B));
    }
}

extern "C" void kernel_launch(void* const* d_in, const int* in_sizes, int n_in,
                              void* d_out, int out_size)
{
    const float* q        = (const float*)d_in[0];
    const float* next_n_q = (const float*)d_in[1];
    const int*   action   = (const int*)  d_in[2];
    const int*   naction  = (const int*)  d_in[3];
    const float* reward   = (const float*)d_in[4];
    const int*   done     = (const int*)  d_in[5];
    const float* replay_q = (const float*)d_in[6];
    const float* weight   = (const float*)d_in[7];

    const int B   = in_sizes[2];
    const int tau = in_sizes[6] / B;
    const int N   = in_sizes[0] / (tau * B);
    const int T   = in_sizes[4] / B;

    float gamma_T = 1.0f;
    for (int i = 0; i < T; ++i) gamma_T *= GAMMA_F;

    float* out = (float*)d_out;

    cudaMemsetAsync(out, 0, sizeof(float), 0);   // zero loss accumulator

    iqn_td_fused_kernel<<<B / BPB, THREADS>>>(q, next_n_q, action, naction,
                                              reward, done, replay_q, weight,
                                              out, B, N, T, gamma_T);
}